// round 3
// baseline (speedup 1.0000x reference)
#include <cuda_runtime.h>
#include <cstdint>

// Depthwise 3x3 conv, stride 1, VALID, C=64.
// x: (16, 64, 512, 512) f32, w: (64, 3, 3) f32 -> out: (16, 64, 510, 510) f32
//
// HBM-roofline kernel (~2.13 GB floor). No shared memory. Each thread owns
// 4 output columns, rolls a 3-row register window down a TILE_H=10 tile
// (halo is L2-absorbed — measured in R1). Math is packed fma.rn.f32x2.
// R3 change: exactly one LDG.128 per thread per row; the 2-float halo comes
// from lane+1 via shfl (lane 31 does a real float2 load). Occupancy pinned
// to 16 blocks/SM (regs <= 32), which was the best measured operating point.

#define TILE_H 10   // 510 = 51 * 10
#define THREADS 128 // 128 threads * 4 cols = 512 >= 510

typedef unsigned long long u64;

__device__ __forceinline__ u64 fpack2(float lo, float hi) {
    u64 d;
    asm("mov.b64 %0, {%1, %2};" : "=l"(d) : "f"(lo), "f"(hi));
    return d;
}

__device__ __forceinline__ u64 fmul2(u64 a, u64 b) {
    u64 d;
    asm("mul.rn.f32x2 %0, %1, %2;" : "=l"(d) : "l"(a), "l"(b));
    return d;
}

__device__ __forceinline__ u64 ffma2(u64 a, u64 b, u64 c) {
    u64 d;
    asm("fma.rn.f32x2 %0, %1, %2, %3;" : "=l"(d) : "l"(a), "l"(b), "l"(c));
    return d;
}

// Load this thread's float4 for one input row and build the 5 overlapping
// f32x2 pairs. Halo floats (cols +4, +5) come from lane+1 via shfl; lane 31
// of each warp loads them directly (2 extra floats per warp per row).
// `last` thread (tid 127, cols 508..511): halo would be OOB at the image
// end; zero it (feeds only the two invalid outputs).
__device__ __forceinline__ void load_row_pairs(const float* __restrict__ p,
                                               int lane, bool last, u64 q[5]) {
    float4 a = *reinterpret_cast<const float4*>(p);
    float v4 = __shfl_down_sync(0xffffffffu, a.x, 1);
    float v5 = __shfl_down_sync(0xffffffffu, a.y, 1);
    if (lane == 31) {
        if (!last) {
            float2 b = *reinterpret_cast<const float2*>(p + 4);
            v4 = b.x;
            v5 = b.y;
        } else {
            v4 = 0.0f;
            v5 = 0.0f;
        }
    }
    q[0] = fpack2(a.x, a.y);
    q[1] = fpack2(a.y, a.z);
    q[2] = fpack2(a.z, a.w);
    q[3] = fpack2(a.w, v4);
    q[4] = fpack2(v4, v5);
}

__global__ void __launch_bounds__(THREADS, 16)
dwconv3x3_kernel(const float* __restrict__ x,
                 const float* __restrict__ w,
                 float* __restrict__ out) {
    const int tile = blockIdx.x;   // 0..50
    const int c    = blockIdx.y;   // 0..63
    const int n    = blockIdx.z;   // 0..15

    const int tid  = threadIdx.x;
    const int lane = tid & 31;
    const int x0   = tid * 4;              // first owned output column
    const bool last = (x0 == 508);         // thread 127: 2 valid outputs only

    const size_t img_off = ((size_t)(n * 64 + c)) * (512 * 512);
    const size_t out_off = ((size_t)(n * 64 + c)) * (510 * 510);
    const float* img = x + img_off;
    float* o = out + out_off;

    const int r0 = tile * TILE_H;          // first output row of this tile

    // Broadcast weights as (w,w) f32x2 pairs.
    const float* wc = w + c * 9;
    u64 wp[9];
#pragma unroll
    for (int i = 0; i < 9; ++i) {
        float wv = __ldg(wc + i);
        wp[i] = fpack2(wv, wv);
    }

    // Rolling 3-row window of overlapping pairs.
    u64 q[3][5];
    load_row_pairs(img + (size_t)(r0 + 0) * 512 + x0, lane, last, q[0]);
    load_row_pairs(img + (size_t)(r0 + 1) * 512 + x0, lane, last, q[1]);

#pragma unroll
    for (int r = 0; r < TILE_H; ++r) {
        const int top = r % 3;
        const int mid = (r + 1) % 3;
        const int bot = (r + 2) % 3;

        load_row_pairs(img + (size_t)(r0 + r + 2) * 512 + x0, lane, last, q[bot]);

        // outputs (x0, x0+1)
        u64 acc01 = fmul2(wp[0], q[top][0]);
        acc01 = ffma2(wp[1], q[top][1], acc01);
        acc01 = ffma2(wp[2], q[top][2], acc01);
        acc01 = ffma2(wp[3], q[mid][0], acc01);
        acc01 = ffma2(wp[4], q[mid][1], acc01);
        acc01 = ffma2(wp[5], q[mid][2], acc01);
        acc01 = ffma2(wp[6], q[bot][0], acc01);
        acc01 = ffma2(wp[7], q[bot][1], acc01);
        acc01 = ffma2(wp[8], q[bot][2], acc01);

        // outputs (x0+2, x0+3)
        u64 acc23 = fmul2(wp[0], q[top][2]);
        acc23 = ffma2(wp[1], q[top][3], acc23);
        acc23 = ffma2(wp[2], q[top][4], acc23);
        acc23 = ffma2(wp[3], q[mid][2], acc23);
        acc23 = ffma2(wp[4], q[mid][3], acc23);
        acc23 = ffma2(wp[5], q[mid][4], acc23);
        acc23 = ffma2(wp[6], q[bot][2], acc23);
        acc23 = ffma2(wp[7], q[bot][3], acc23);
        acc23 = ffma2(wp[8], q[bot][4], acc23);

        // Row stride 510*4 = 2040 B is 8-byte aligned -> STG.64 stores.
        float* orow = o + (size_t)(r0 + r) * 510 + x0;
        *reinterpret_cast<u64*>(orow) = acc01;
        if (!last) {
            *reinterpret_cast<u64*>(orow + 2) = acc23;
        }
    }
}

extern "C" void kernel_launch(void* const* d_in, const int* in_sizes, int n_in,
                              void* d_out, int out_size) {
    const float* x = (const float*)d_in[0];
    const float* w = (const float*)d_in[1];
    // Defensive: metadata order is (x, weight); swap if sizes say otherwise.
    if (n_in >= 2 && in_sizes[0] < in_sizes[1]) {
        const float* t = x; x = w; w = t;
    }
    float* out = (float*)d_out;

    dim3 grid(51, 64, 16); // 510/TILE_H row tiles, C, N
    dwconv3x3_kernel<<<grid, THREADS>>>(x, w, out);
}

// round 4
// speedup vs baseline: 1.0667x; 1.0667x over previous
#include <cuda_runtime.h>
#include <cstdint>

// Depthwise 3x3 conv, stride 1, VALID, C=64.
// x: (16, 64, 512, 512) f32, w: (64, 3, 3) f32 -> out: (16, 64, 510, 510) f32
//
// HBM-roofline kernel (~2.13 GB floor). No shared memory, no shfl.
// R4: rolling PARTIAL-SUM formulation. For input row i, compute its three
// horizontal 3-tap convolutions h0/h1/h2 and accumulate into the 3 pending
// output rows (out[r] = h0[r] + h1[r+1] + h2[r+2]). Live state is 3 accum
// sets (12 regs) instead of a 3-row pair window (30 regs) — the freed
// register pressure lets ptxas front-batch the independent LDGs across the
// unrolled row loop (higher MLP -> higher achieved HBM).
// Math is packed fma.rn.f32x2; weights kept scalar, packed at use (CSE'd).

#define TILE_H 10   // 510 = 51 * 10
#define THREADS 128 // 128 threads * 4 cols = 512 >= 510

typedef unsigned long long u64;

__device__ __forceinline__ u64 fpack2(float lo, float hi) {
    u64 d;
    asm("mov.b64 %0, {%1, %2};" : "=l"(d) : "f"(lo), "f"(hi));
    return d;
}

__device__ __forceinline__ u64 fmul2(u64 a, u64 b) {
    u64 d;
    asm("mul.rn.f32x2 %0, %1, %2;" : "=l"(d) : "l"(a), "l"(b));
    return d;
}

__device__ __forceinline__ u64 ffma2(u64 a, u64 b, u64 c) {
    u64 d;
    asm("fma.rn.f32x2 %0, %1, %2, %3;" : "=l"(d) : "l"(a), "l"(b), "l"(c));
    return d;
}

// Load 6 consecutive floats at p (16B aligned) -> 5 overlapping f32x2 pairs.
// `last` thread (cols 508..511): cols 512/513 may be OOB at the image end;
// zero them (they only feed the two invalid outputs 510/511).
__device__ __forceinline__ void load_row_pairs(const float* __restrict__ p,
                                               bool last, u64 q[5]) {
    float4 a = *reinterpret_cast<const float4*>(p);
    float v4 = 0.0f, v5 = 0.0f;
    if (!last) {
        float2 b = *reinterpret_cast<const float2*>(p + 4);
        v4 = b.x;
        v5 = b.y;
    }
    q[0] = fpack2(a.x, a.y);
    q[1] = fpack2(a.y, a.z);
    q[2] = fpack2(a.z, a.w);
    q[3] = fpack2(a.w, v4);
    q[4] = fpack2(v4, v5);
}

__global__ void __launch_bounds__(THREADS, 16)
dwconv3x3_kernel(const float* __restrict__ x,
                 const float* __restrict__ w,
                 float* __restrict__ out) {
    const int tile = blockIdx.x;   // 0..50
    const int c    = blockIdx.y;   // 0..63
    const int n    = blockIdx.z;   // 0..15

    const int tid = threadIdx.x;
    const int x0  = tid * 4;               // first owned output column
    const bool last = (x0 == 508);         // thread 127: 2 valid outputs only

    const size_t img_off = ((size_t)(n * 64 + c)) * (512 * 512);
    const size_t out_off = ((size_t)(n * 64 + c)) * (510 * 510);
    const float* img = x + img_off;
    float* o = out + out_off;

    const int r0 = tile * TILE_H;          // first output row of this tile

    // Scalar weights; pack (w,w) pairs at use -> ptxas decides residency.
    const float* wc = w + c * 9;
    float wv[9];
#pragma unroll
    for (int i = 0; i < 9; ++i) wv[i] = __ldg(wc + i);

#define W(i) fpack2(wv[i], wv[i])

    // Three pending output accumulators, 2 f32x2 each (4 columns).
    u64 acc[3][2];
    u64 q[5];

    // FRESH: acc[C] = h0(row)   (weight row 0)
#define FRESH(C)                                                               \
    acc[C][0] = fmul2(W(0), q[0]);                                             \
    acc[C][0] = ffma2(W(1), q[1], acc[C][0]);                                  \
    acc[C][0] = ffma2(W(2), q[2], acc[C][0]);                                  \
    acc[C][1] = fmul2(W(0), q[2]);                                             \
    acc[C][1] = ffma2(W(1), q[3], acc[C][1]);                                  \
    acc[C][1] = ffma2(W(2), q[4], acc[C][1]);

    // MIDA: acc[B] += h1(row)   (weight row 1)
#define MIDA(B)                                                                \
    acc[B][0] = ffma2(W(3), q[0], acc[B][0]);                                  \
    acc[B][0] = ffma2(W(4), q[1], acc[B][0]);                                  \
    acc[B][0] = ffma2(W(5), q[2], acc[B][0]);                                  \
    acc[B][1] = ffma2(W(3), q[2], acc[B][1]);                                  \
    acc[B][1] = ffma2(W(4), q[3], acc[B][1]);                                  \
    acc[B][1] = ffma2(W(5), q[4], acc[B][1]);

    // DONE: acc[A] += h2(row)   (weight row 2) -> output row complete
#define DONE(A)                                                                \
    acc[A][0] = ffma2(W(6), q[0], acc[A][0]);                                  \
    acc[A][0] = ffma2(W(7), q[1], acc[A][0]);                                  \
    acc[A][0] = ffma2(W(8), q[2], acc[A][0]);                                  \
    acc[A][1] = ffma2(W(6), q[2], acc[A][1]);                                  \
    acc[A][1] = ffma2(W(7), q[3], acc[A][1]);                                  \
    acc[A][1] = ffma2(W(8), q[4], acc[A][1]);

    // Prologue: input rows r0 and r0+1 (no completed outputs yet).
    // Role schedule (iteration i over input rows): A=i%3 completes,
    // B=(i+1)%3 gets mid, C=(i+2)%3 starts fresh.
    load_row_pairs(img + (size_t)(r0 + 0) * 512 + x0, last, q);
    FRESH(2)                                   // completes at i=2
    load_row_pairs(img + (size_t)(r0 + 1) * 512 + x0, last, q);
    MIDA(2)
    FRESH(0)                                   // completes at i=3

    // Main: input rows r0+2 .. r0+11; output row r0+i-2 completes at i.
#pragma unroll
    for (int i = 2; i < TILE_H + 2; ++i) {
        const int A = i % 3;
        const int B = (i + 1) % 3;
        const int C = (i + 2) % 3;

        load_row_pairs(img + (size_t)(r0 + i) * 512 + x0, last, q);
        DONE(A)
        MIDA(B)
        FRESH(C)

        // Row stride 510*4 = 2040 B is 8-byte aligned -> STG.64 stores.
        float* orow = o + (size_t)(r0 + i - 2) * 510 + x0;
        *reinterpret_cast<u64*>(orow) = acc[A][0];
        if (!last) {
            *reinterpret_cast<u64*>(orow + 2) = acc[A][1];
        }
    }

#undef FRESH
#undef MIDA
#undef DONE
#undef W
}

extern "C" void kernel_launch(void* const* d_in, const int* in_sizes, int n_in,
                              void* d_out, int out_size) {
    const float* x = (const float*)d_in[0];
    const float* w = (const float*)d_in[1];
    // Defensive: metadata order is (x, weight); swap if sizes say otherwise.
    if (n_in >= 2 && in_sizes[0] < in_sizes[1]) {
        const float* t = x; x = w; w = t;
    }
    float* out = (float*)d_out;

    dim3 grid(51, 64, 16); // 510/TILE_H row tiles, C, N
    dwconv3x3_kernel<<<grid, THREADS>>>(x, w, out);
}